// round 7
// baseline (speedup 1.0000x reference)
#include <cuda_runtime.h>
#include <cuda_bf16.h>
#include <cstdint>
#include <cstdio>

// ---------------------------------------------------------------------------
// Problem constants
// ---------------------------------------------------------------------------
#define VOCAB   100000
#define EMBED   100
#define HID     128
#define NOISE_D 10
#define BATCH   2048
#define KDIM    (EMBED + NOISE_D)   // 110
#define NT      782                 // ceil(VOCAB/128); 782*128 = 100096
#define MT      16                  // BATCH/128

// dynamic smem layout for the GEMM kernel
#define SMEM_A_OFF    0            // 128x128 bf16  (32768 B)
#define SMEM_B_OFF    32768        // 128x128 bf16  (32768 B)
#define SMEM_BIAS_OFF 65536        // 128 f32       (512 B)
#define SMEM_RED_OFF  66048        // 4*128 f32     (2048 B)
#define SMEM_BYTES    68096

// ---------------------------------------------------------------------------
// Scratch (device globals: no allocation in kernel_launch)
// ---------------------------------------------------------------------------
__device__ __align__(16) __nv_bfloat16 g_hb[BATCH * HID];   // h in bf16
__device__ __align__(16) __nv_bfloat16 g_wb[VOCAB * HID];   // fc_w in bf16
__device__ float g_partial[NT * BATCH];                     // per n-tile row sums
__device__ float g_rowsum[BATCH];                           // final denominators

// ---------------------------------------------------------------------------
// PTX helpers
// ---------------------------------------------------------------------------
__device__ __forceinline__ void ldsm4(uint32_t* r, uint32_t addr) {
    asm volatile("ldmatrix.sync.aligned.m8n8.x4.shared.b16 {%0,%1,%2,%3}, [%4];\n"
                 : "=r"(r[0]), "=r"(r[1]), "=r"(r[2]), "=r"(r[3]) : "r"(addr));
}

__device__ __forceinline__ void mma16816(float* c, const uint32_t* a, const uint32_t* b) {
    asm volatile(
        "mma.sync.aligned.m16n8k16.row.col.f32.bf16.bf16.f32 "
        "{%0,%1,%2,%3}, {%4,%5,%6,%7}, {%8,%9}, {%0,%1,%2,%3};\n"
        : "+f"(c[0]), "+f"(c[1]), "+f"(c[2]), "+f"(c[3])
        : "r"(a[0]), "r"(a[1]), "r"(a[2]), "r"(a[3]), "r"(b[0]), "r"(b[1]));
}

// ---------------------------------------------------------------------------
// Kernel 1: fc_w (f32) -> bf16
// ---------------------------------------------------------------------------
__global__ void k_convert(const float* __restrict__ w) {
    int idx = blockIdx.x * 256 + threadIdx.x;       // one float4 per thread
    if (idx < VOCAB * HID / 4) {
        float4 v = ((const float4*)w)[idx];
        __nv_bfloat162 a = __floats2bfloat162_rn(v.x, v.y);
        __nv_bfloat162 b = __floats2bfloat162_rn(v.z, v.w);
        uint2 u;
        u.x = *reinterpret_cast<unsigned*>(&a);
        u.y = *reinterpret_cast<unsigned*>(&b);
        ((uint2*)g_wb)[idx] = u;
    }
}

// ---------------------------------------------------------------------------
// Kernel 2: embedding concat + LSTM step -> h (bf16).
// h0 = 0 kills W_hh; c0 = 0 kills the f gate. h = sig(o)*tanh(sig(i)*tanh(g)).
// Gate rows (PyTorch order i,f,g,o): i=j, g=256+j, o=384+j.
// ---------------------------------------------------------------------------
__global__ void k_hidden(const int* __restrict__ x, const float* __restrict__ noise,
                         const float* __restrict__ emb, const float* __restrict__ W_ih,
                         const float* __restrict__ b_ih, const float* __restrict__ b_hh) {
    __shared__ float comb[16][112];
    int b0 = blockIdx.x * 16;
    for (int idx = threadIdx.x; idx < 16 * KDIM; idx += 256) {
        int r = idx / KDIM, k = idx % KDIM;
        int b = b0 + r;
        comb[r][k] = (k < EMBED) ? emb[(size_t)x[b] * EMBED + k]
                                 : noise[b * NOISE_D + (k - EMBED)];
    }
    __syncthreads();

    int j = threadIdx.x & 127;
    int half = threadIdx.x >> 7;     // handles 8 batch rows
    float ai[8], ag[8], ao[8];
#pragma unroll
    for (int r = 0; r < 8; ++r) { ai[r] = 0.f; ag[r] = 0.f; ao[r] = 0.f; }

    const float* wi = W_ih + (size_t)j * KDIM;
    const float* wg = W_ih + (size_t)(256 + j) * KDIM;
    const float* wo = W_ih + (size_t)(384 + j) * KDIM;
    for (int k = 0; k < KDIM; ++k) {
        float vi = wi[k], vg = wg[k], vo = wo[k];
#pragma unroll
        for (int r = 0; r < 8; ++r) {
            float c = comb[half * 8 + r][k];
            ai[r] += vi * c; ag[r] += vg * c; ao[r] += vo * c;
        }
    }
    float bi = b_ih[j] + b_hh[j];
    float bg = b_ih[256 + j] + b_hh[256 + j];
    float bo = b_ih[384 + j] + b_hh[384 + j];
#pragma unroll
    for (int r = 0; r < 8; ++r) {
        float iv = 1.f / (1.f + __expf(-(ai[r] + bi)));
        float gv = tanhf(ag[r] + bg);
        float ov = 1.f / (1.f + __expf(-(ao[r] + bo)));
        float h  = ov * tanhf(iv * gv);
        g_hb[(size_t)(b0 + half * 8 + r) * HID + j] = __float2bfloat16(h);
    }
}

// ---------------------------------------------------------------------------
// Kernel 3/5: 128x128 bf16 MMA tile of logits = h @ fc_w^T (+ fc_b).
// PASS 0: per-(row, n-tile) sum of exp(logit) -> g_partial (no big write).
// PASS 1: recompute, write exp(logit)/rowsum to out.
// Note |logit| << 80, so exp() without max-subtraction is numerically safe.
// ---------------------------------------------------------------------------
template <int PASS>
__global__ void __launch_bounds__(256)
k_gemm(const float* __restrict__ fc_b, float* __restrict__ out) {
    extern __shared__ unsigned char smem[];
    __nv_bfloat16* sA = (__nv_bfloat16*)(smem + SMEM_A_OFF);
    __nv_bfloat16* sB = (__nv_bfloat16*)(smem + SMEM_B_OFF);
    float* sbias = (float*)(smem + SMEM_BIAS_OFF);
    float* sred  = (float*)(smem + SMEM_RED_OFF);

    const int tid = threadIdx.x;
    const int nb0 = blockIdx.x * 128;
    const int mb0 = blockIdx.y * 128;

    if (tid < 128) {
        int n = nb0 + tid;
        sbias[tid] = (n < VOCAB) ? fc_b[n] : 0.f;
        if (PASS == 1) sred[tid] = 1.0f / g_rowsum[mb0 + tid];
    }

    // Load A (h) and B (fc_w) tiles, XOR-swizzled in 16B chunks: 8 chunks/row phase.
    {
        const uint4* gA = (const uint4*)g_hb;  // 16 uint4 per 128-col bf16 row
        const uint4* gB = (const uint4*)g_wb;
        uint4* s4A = (uint4*)sA;
        uint4* s4B = (uint4*)sB;
#pragma unroll
        for (int it = 0; it < 8; ++it) {
            int idx = tid + it * 256;
            int row = idx >> 4, ch = idx & 15;
            s4A[(row << 4) + (ch ^ (row & 7))] = gA[(size_t)(mb0 + row) * 16 + ch];
            int n = nb0 + row;
            uint4 v = make_uint4(0u, 0u, 0u, 0u);
            if (n < VOCAB) v = gB[(size_t)n * 16 + ch];
            s4B[(row << 4) + (ch ^ (row & 7))] = v;
        }
    }
    __syncthreads();

    const int warp = tid >> 5, lane = tid & 31;
    const int wm = warp >> 2, wn = warp & 3;      // 2x4 warp grid, 64x32 warp tile
    const int gid = lane >> 2, tig = lane & 3;

    uint32_t aBase = (uint32_t)__cvta_generic_to_shared(sA);
    uint32_t bBase = (uint32_t)__cvta_generic_to_shared(sB);

    float acc[4][4][4];
#pragma unroll
    for (int i = 0; i < 4; ++i)
#pragma unroll
        for (int jn = 0; jn < 4; ++jn)
#pragma unroll
            for (int e = 0; e < 4; ++e) acc[i][jn][e] = 0.f;

    const int aRow  = wm * 64 + (lane & 15);
    const int aHalf = lane >> 4;
    const int bN    = wn * 32 + ((lane & 16) >> 1) + (lane & 7);
    const int bHalf = (lane >> 3) & 1;

#pragma unroll
    for (int ks = 0; ks < 8; ++ks) {
        int c0 = ks << 1;
        uint32_t af[4][4];
#pragma unroll
        for (int mt = 0; mt < 4; ++mt) {
            int r = aRow + mt * 16;
            int ch = c0 + aHalf;
            ldsm4(af[mt], aBase + (r << 8) + ((ch ^ (r & 7)) << 4));
        }
        uint32_t bfr[2][4];
#pragma unroll
        for (int p = 0; p < 2; ++p) {
            int n = bN + p * 16;
            int ch = c0 + bHalf;
            ldsm4(bfr[p], bBase + (n << 8) + ((ch ^ (n & 7)) << 4));
        }
#pragma unroll
        for (int mt = 0; mt < 4; ++mt)
#pragma unroll
            for (int nt = 0; nt < 4; ++nt)
                mma16816(acc[mt][nt], af[mt], &bfr[nt >> 1][(nt & 1) * 2]);
    }

    if (PASS == 0) {
        // Per-thread sums over its 8 owned rows, then tig-shuffle, then
        // per-warp slots in smem, then a deterministic 4-way sum.
        float ps[8];
#pragma unroll
        for (int i = 0; i < 8; ++i) ps[i] = 0.f;
#pragma unroll
        for (int mt = 0; mt < 4; ++mt)
#pragma unroll
            for (int nt = 0; nt < 4; ++nt)
#pragma unroll
                for (int e = 0; e < 4; ++e) {
                    int col = wn * 32 + nt * 8 + 2 * tig + (e & 1);
                    int n = nb0 + col;
                    if (n < VOCAB)
                        ps[mt * 2 + (e >> 1)] += __expf(acc[mt][nt][e] + sbias[col]);
                }
#pragma unroll
        for (int i = 0; i < 8; ++i) {
            ps[i] += __shfl_xor_sync(0xffffffffu, ps[i], 1);
            ps[i] += __shfl_xor_sync(0xffffffffu, ps[i], 2);
        }
        if (tig == 0) {
#pragma unroll
            for (int i = 0; i < 8; ++i) {
                int mt = i >> 1, h = i & 1;
                int row = wm * 64 + mt * 16 + gid + 8 * h;
                sred[wn * 128 + row] = ps[i];   // each slot written exactly once
            }
        }
        __syncthreads();
        if (tid < 128) {
            float s = sred[tid] + sred[128 + tid] + sred[256 + tid] + sred[384 + tid];
            g_partial[(size_t)blockIdx.x * BATCH + mb0 + tid] = s;
        }
    } else {
#pragma unroll
        for (int mt = 0; mt < 4; ++mt)
#pragma unroll
            for (int nt = 0; nt < 4; ++nt)
#pragma unroll
                for (int h = 0; h < 2; ++h) {
                    int col0 = wn * 32 + nt * 8 + 2 * tig;
                    int n = nb0 + col0;
                    if (n < VOCAB) {
                        int row = wm * 64 + mt * 16 + gid + 8 * h;
                        float r = sred[row];
                        float2 v;
                        v.x = __expf(acc[mt][nt][h * 2 + 0] + sbias[col0 + 0]) * r;
                        v.y = __expf(acc[mt][nt][h * 2 + 1] + sbias[col0 + 1]) * r;
                        *(float2*)&out[(size_t)(mb0 + row) * VOCAB + n] = v;
                    }
                }
    }
}

// ---------------------------------------------------------------------------
// Kernel 4: deterministic fixed-order reduction of partials -> g_rowsum
// ---------------------------------------------------------------------------
__global__ void k_reduce() {
    __shared__ float sh[256];
    int row = blockIdx.x;
    float s = 0.f;
    for (int j = threadIdx.x; j < NT; j += 256)
        s += g_partial[(size_t)j * BATCH + row];
    sh[threadIdx.x] = s;
    __syncthreads();
    for (int off = 128; off > 0; off >>= 1) {
        if (threadIdx.x < off) sh[threadIdx.x] += sh[threadIdx.x + off];
        __syncthreads();
    }
    if (threadIdx.x == 0) g_rowsum[row] = sh[0];
}

// ---------------------------------------------------------------------------
// kernel_launch
// ---------------------------------------------------------------------------
extern "C" void kernel_launch(void* const* d_in, const int* in_sizes, int n_in,
                              void* d_out, int out_size) {
    // Robust input identification by element count (all counts distinct except
    // b_ih/b_hh, whose order doesn't matter: only their sum is used).
    const int* x = nullptr;
    const float *noise = nullptr, *emb = nullptr, *W_ih = nullptr;
    const float *b_ih = nullptr, *b_hh = nullptr, *fc_w = nullptr, *fc_b = nullptr;
    for (int i = 0; i < n_in; ++i) {
        switch (in_sizes[i]) {
            case BATCH:            x     = (const int*)d_in[i];   break; // 2048
            case BATCH * NOISE_D:  noise = (const float*)d_in[i]; break; // 20480
            case VOCAB * EMBED:    emb   = (const float*)d_in[i]; break; // 10,000,000
            case 4 * HID * KDIM:   W_ih  = (const float*)d_in[i]; break; // 56320
            case 4 * HID * HID:    /* W_hh unused (h0 = 0) */     break; // 65536
            case 4 * HID:          if (!b_ih) b_ih = (const float*)d_in[i];
                                   else       b_hh = (const float*)d_in[i]; break;
            case VOCAB * HID:      fc_w  = (const float*)d_in[i]; break; // 12,800,000
            case VOCAB:            fc_b  = (const float*)d_in[i]; break; // 100000
            default: break;
        }
    }
    float* out = (float*)d_out;

    // One-time host config (runs on the pre-capture correctness call).
    static bool s_init = []() {
        cudaFuncSetAttribute(k_gemm<0>, cudaFuncAttributeMaxDynamicSharedMemorySize, SMEM_BYTES);
        cudaFuncSetAttribute(k_gemm<1>, cudaFuncAttributeMaxDynamicSharedMemorySize, SMEM_BYTES);
        return true;
    }();
    (void)s_init;

    k_convert<<<(VOCAB * HID / 4 + 255) / 256, 256>>>(fc_w);
    k_hidden<<<BATCH / 16, 256>>>(x, noise, emb, W_ih, b_ih, b_hh);

    dim3 grid(NT, MT);
    k_gemm<0><<<grid, 256, SMEM_BYTES>>>(fc_b, out);
    k_reduce<<<BATCH, 256>>>();
    k_gemm<1><<<grid, 256, SMEM_BYTES>>>(fc_b, out);
}

// round 10
// speedup vs baseline: 1.0832x; 1.0832x over previous
#include <cuda_runtime.h>
#include <cuda_bf16.h>
#include <cstdint>

// ---------------------------------------------------------------------------
// Problem constants
// ---------------------------------------------------------------------------
#define VOCAB   100000
#define EMBED   100
#define HID     128
#define NOISE_D 10
#define BATCH   2048
#define KDIM    (EMBED + NOISE_D)   // 110
#define NT      782                 // ceil(VOCAB/128); 782*128 = 100096
#define MT      16                  // BATCH/128
#define NPAD    (NT * 128)          // fc_w rows padded with zeros
#define NUNITS  (NT * 2)            // work units: (strip, half of 16 m-tiles)
#define GRID_GEMM 296               // 148 SMs x 2 resident CTAs

// smem layout (bytes). B strip persistent; A double-buffered.
#define SB_OFF     0               // 128x128 bf16 = 32768
#define SA0_OFF    32768           // 32768
#define SA1_OFF    65536           // 32768
#define SBIAS_OFF  98304           // 128 f32
#define SRINV_OFF  98816           // 128 f32
#define SRED_OFF   99328           // 512 f32 (2048 B)
#define SUNIT_OFF  101376          // 16 B broadcast slot
#define SMEM_BYTES 101392

// ---------------------------------------------------------------------------
// Scratch (device globals: no allocation anywhere)
// ---------------------------------------------------------------------------
__device__ __align__(16) __nv_bfloat16 g_hb[BATCH * HID];   // h in bf16
__device__ __align__(16) __nv_bfloat16 g_wb[NPAD * HID];    // fc_w bf16, zero-padded
__device__ float g_partial[NT * BATCH];                     // per n-tile row sums
__device__ float g_rinv[BATCH];                             // 1 / rowsum
__device__ unsigned g_tick[2];                              // work tickets (per pass)

// ---------------------------------------------------------------------------
// PTX helpers (all sm_90-safe: no 'a'-gated features)
// ---------------------------------------------------------------------------
__device__ __forceinline__ void ldsm4(uint32_t* r, uint32_t addr) {
    asm volatile("ldmatrix.sync.aligned.m8n8.x4.shared.b16 {%0,%1,%2,%3}, [%4];\n"
                 : "=r"(r[0]), "=r"(r[1]), "=r"(r[2]), "=r"(r[3]) : "r"(addr));
}
__device__ __forceinline__ void mma16816(float* c, const uint32_t* a, const uint32_t* b) {
    asm volatile(
        "mma.sync.aligned.m16n8k16.row.col.f32.bf16.bf16.f32 "
        "{%0,%1,%2,%3}, {%4,%5,%6,%7}, {%8,%9}, {%0,%1,%2,%3};\n"
        : "+f"(c[0]), "+f"(c[1]), "+f"(c[2]), "+f"(c[3])
        : "r"(a[0]), "r"(a[1]), "r"(a[2]), "r"(a[3]), "r"(b[0]), "r"(b[1]));
}
__device__ __forceinline__ void cp16(uint32_t dst, const void* src) {
    asm volatile("cp.async.cg.shared.global [%0], [%1], 16;" :: "r"(dst), "l"(src));
}
__device__ __forceinline__ void cp_commit() { asm volatile("cp.async.commit_group;"); }
__device__ __forceinline__ void cp_wait0()  { asm volatile("cp.async.wait_group 0;" ::: "memory"); }

// ---------------------------------------------------------------------------
// Kernel 1: fc_w (f32) -> bf16 with zero padding; also resets work tickets
// ---------------------------------------------------------------------------
__global__ void k_convert(const float* __restrict__ w) {
    if (blockIdx.x == 0 && threadIdx.x == 0) { g_tick[0] = 0u; g_tick[1] = 0u; }
    int idx = blockIdx.x * 256 + threadIdx.x;       // one uint2 (4 bf16) per thread
    if (idx < NPAD * HID / 4) {
        uint2 u = make_uint2(0u, 0u);
        if (idx < VOCAB * HID / 4) {
            float4 v = ((const float4*)w)[idx];
            __nv_bfloat162 a = __floats2bfloat162_rn(v.x, v.y);
            __nv_bfloat162 b = __floats2bfloat162_rn(v.z, v.w);
            u.x = *reinterpret_cast<unsigned*>(&a);
            u.y = *reinterpret_cast<unsigned*>(&b);
        }
        ((uint2*)g_wb)[idx] = u;
    }
}

// ---------------------------------------------------------------------------
// Kernel 2: embedding concat + LSTM step -> h (bf16).
// h0 = 0 kills W_hh; c0 = 0 kills the f gate. h = sig(o)*tanh(sig(i)*tanh(g)).
// ---------------------------------------------------------------------------
__global__ void k_hidden(const int* __restrict__ x, const float* __restrict__ noise,
                         const float* __restrict__ emb, const float* __restrict__ W_ih,
                         const float* __restrict__ b_ih, const float* __restrict__ b_hh) {
    __shared__ float comb[16][112];
    int b0 = blockIdx.x * 16;
    for (int idx = threadIdx.x; idx < 16 * KDIM; idx += 256) {
        int r = idx / KDIM, k = idx % KDIM;
        int b = b0 + r;
        comb[r][k] = (k < EMBED) ? emb[(size_t)x[b] * EMBED + k]
                                 : noise[b * NOISE_D + (k - EMBED)];
    }
    __syncthreads();

    int j = threadIdx.x & 127;
    int grp = threadIdx.x >> 7;      // handles 8 batch rows
    float ai[8], ag[8], ao[8];
#pragma unroll
    for (int r = 0; r < 8; ++r) { ai[r] = 0.f; ag[r] = 0.f; ao[r] = 0.f; }

    const float* wi = W_ih + (size_t)j * KDIM;
    const float* wg = W_ih + (size_t)(256 + j) * KDIM;
    const float* wo = W_ih + (size_t)(384 + j) * KDIM;
    for (int k = 0; k < KDIM; ++k) {
        float vi = wi[k], vg = wg[k], vo = wo[k];
#pragma unroll
        for (int r = 0; r < 8; ++r) {
            float c = comb[grp * 8 + r][k];
            ai[r] += vi * c; ag[r] += vg * c; ao[r] += vo * c;
        }
    }
    float bi = b_ih[j] + b_hh[j];
    float bg = b_ih[256 + j] + b_hh[256 + j];
    float bo = b_ih[384 + j] + b_hh[384 + j];
#pragma unroll
    for (int r = 0; r < 8; ++r) {
        float iv = 1.f / (1.f + __expf(-(ai[r] + bi)));
        float gv = tanhf(ag[r] + bg);
        float ov = 1.f / (1.f + __expf(-(ao[r] + bo)));
        float h  = ov * tanhf(iv * gv);
        g_hb[(size_t)(b0 + grp * 8 + r) * HID + j] = __float2bfloat16(h);
    }
}

// ---------------------------------------------------------------------------
// Kernel 3/5: persistent mma.sync GEMM. Work unit = (fc_w 128-col strip, half
// of the 16 m-tiles): B strip loaded to smem ONCE per unit and reused for 8
// m-tiles; A tiles double-buffered via cp.async prefetch.
// PASS 0: per-(row, n-tile) sum of exp(logit) -> g_partial (no big write).
// PASS 1: recompute, write exp(logit) * (1/rowsum) with streaming stores.
// |logit| is O(1), so exp without max-subtraction is numerically safe.
// ---------------------------------------------------------------------------
template <int PASS>
__global__ void __launch_bounds__(256, 2)
k_gemm(const float* __restrict__ fc_b, float* __restrict__ out) {
    extern __shared__ unsigned char smem[];
    uint32_t sbase = (uint32_t)__cvta_generic_to_shared(smem);
    float* sbias = (float*)(smem + SBIAS_OFF);
    float* srinv = (float*)(smem + SRINV_OFF);
    float* sred  = (float*)(smem + SRED_OFF);
    unsigned* sunit = (unsigned*)(smem + SUNIT_OFF);

    const int tid = threadIdx.x;
    const int warp = tid >> 5, lane = tid & 31;
    const int wm = warp >> 2, wn = warp & 3;      // 2x4 warp grid, 64x32 warp tile
    const int gid = lane >> 2, tig = lane & 3;

    const uint4* gA = (const uint4*)g_hb;   // 16 uint4 per 128-col bf16 row
    const uint4* gB = (const uint4*)g_wb;

    // this thread's 8 swizzled 16B chunks (same indexing as the tile layout)
    const int cr = tid >> 4, cch = tid & 15;            // base row/chunk
    // chunk byte offset within a tile for (row, ch): ((row<<4) + (ch^(row&7))) << 4

    const int aRow  = wm * 64 + (lane & 15);
    const int aHalf = lane >> 4;
    const int bN    = wn * 32 + ((lane & 16) >> 1) + (lane & 7);
    const int bHalf = (lane >> 3) & 1;
    const uint32_t bBase = sbase + SB_OFF;

    for (;;) {
        if (tid == 0) *sunit = atomicAdd(&g_tick[PASS], 1u);
        __syncthreads();
        unsigned u = *sunit;
        if (u >= NUNITS) break;
        const int jn  = (int)(u >> 1);
        const int nb0 = jn << 7;
        const int jm0 = (int)(u & 1u) << 3;

        // Issue B strip + first A tile (cp.async, swizzled dst), load bias.
#pragma unroll
        for (int i = 0; i < 8; ++i) {
            int r = cr + i * 16, ch = cch;
            uint32_t so = (uint32_t)(((r << 4) + (ch ^ (r & 7))) << 4);
            cp16(sbase + SB_OFF + so,  gB + (size_t)(nb0 + r) * 16 + ch);  // padded: no guard
            cp16(sbase + SA0_OFF + so, gA + (size_t)((jm0 << 7) + r) * 16 + ch);
        }
        cp_commit();
        if (tid < 128) {
            int n = nb0 + tid;
            sbias[tid] = (n < VOCAB) ? fc_b[n] : 0.f;
        }
        cp_wait0();
        __syncthreads();

        for (int jj = 0; jj < 8; ++jj) {
            const int jm = jm0 + jj;
            const int mb0 = jm << 7;
            const uint32_t aBase = sbase + ((jj & 1) ? SA1_OFF : SA0_OFF);

            if (PASS == 1 && tid < 128) srinv[tid] = g_rinv[mb0 + tid];
            if (jj < 7) {
                const uint32_t aNext = sbase + ((jj & 1) ? SA0_OFF : SA1_OFF);
                const int mb1 = (jm + 1) << 7;
#pragma unroll
                for (int i = 0; i < 8; ++i) {
                    int r = cr + i * 16, ch = cch;
                    uint32_t so = (uint32_t)(((r << 4) + (ch ^ (r & 7))) << 4);
                    cp16(aNext + so, gA + (size_t)(mb1 + r) * 16 + ch);
                }
                cp_commit();
            }
            __syncthreads();   // current A + srinv visible; prefetch in flight

            float acc[4][4][4];
#pragma unroll
            for (int i = 0; i < 4; ++i)
#pragma unroll
                for (int jx = 0; jx < 4; ++jx)
#pragma unroll
                    for (int e = 0; e < 4; ++e) acc[i][jx][e] = 0.f;

#pragma unroll
            for (int ks = 0; ks < 8; ++ks) {
                int c0 = ks << 1;
                uint32_t af[4][4];
#pragma unroll
                for (int mt = 0; mt < 4; ++mt) {
                    int r = aRow + mt * 16;
                    int ch = c0 + aHalf;
                    ldsm4(af[mt], aBase + (r << 8) + ((ch ^ (r & 7)) << 4));
                }
                uint32_t bfr[2][4];
#pragma unroll
                for (int p = 0; p < 2; ++p) {
                    int n = bN + p * 16;
                    int ch = c0 + bHalf;
                    ldsm4(bfr[p], bBase + (n << 8) + ((ch ^ (n & 7)) << 4));
                }
#pragma unroll
                for (int mt = 0; mt < 4; ++mt)
#pragma unroll
                    for (int nt = 0; nt < 4; ++nt)
                        mma16816(acc[mt][nt], af[mt], &bfr[nt >> 1][(nt & 1) * 2]);
            }

            if (PASS == 0) {
                float ps[8];
#pragma unroll
                for (int i = 0; i < 8; ++i) ps[i] = 0.f;
#pragma unroll
                for (int mt = 0; mt < 4; ++mt)
#pragma unroll
                    for (int nt = 0; nt < 4; ++nt)
#pragma unroll
                        for (int e = 0; e < 4; ++e) {
                            int col = wn * 32 + nt * 8 + 2 * tig + (e & 1);
                            int n = nb0 + col;
                            if (n < VOCAB)
                                ps[mt * 2 + (e >> 1)] += __expf(acc[mt][nt][e] + sbias[col]);
                        }
#pragma unroll
                for (int i = 0; i < 8; ++i) {
                    ps[i] += __shfl_xor_sync(0xffffffffu, ps[i], 1);
                    ps[i] += __shfl_xor_sync(0xffffffffu, ps[i], 2);
                }
                if (tig == 0) {
#pragma unroll
                    for (int i = 0; i < 8; ++i) {
                        int mt = i >> 1, h = i & 1;
                        int row = wm * 64 + mt * 16 + gid + 8 * h;
                        sred[wn * 128 + row] = ps[i];
                    }
                }
                __syncthreads();
                if (tid < 128)
                    g_partial[(size_t)jn * BATCH + mb0 + tid] =
                        sred[tid] + sred[128 + tid] + sred[256 + tid] + sred[384 + tid];
            } else {
#pragma unroll
                for (int mt = 0; mt < 4; ++mt)
#pragma unroll
                    for (int nt = 0; nt < 4; ++nt)
#pragma unroll
                        for (int h = 0; h < 2; ++h) {
                            int col0 = wn * 32 + nt * 8 + 2 * tig;
                            int n = nb0 + col0;
                            if (n < VOCAB) {
                                int row = wm * 64 + mt * 16 + gid + 8 * h;
                                float rv = srinv[row];
                                float2 v;
                                v.x = __expf(acc[mt][nt][h * 2 + 0] + sbias[col0 + 0]) * rv;
                                v.y = __expf(acc[mt][nt][h * 2 + 1] + sbias[col0 + 1]) * rv;
                                __stcs((float2*)&out[(size_t)(mb0 + row) * VOCAB + n], v);
                            }
                        }
            }
            if (jj < 7) cp_wait0();
            __syncthreads();   // done with this A buffer / sred / srinv
        }
    }
}

// ---------------------------------------------------------------------------
// Kernel 4: deterministic fixed-order reduction -> reciprocal denominators
// ---------------------------------------------------------------------------
__global__ void k_reduce() {
    __shared__ float sh[256];
    int row = blockIdx.x;
    float s = 0.f;
    for (int j = threadIdx.x; j < NT; j += 256)
        s += g_partial[(size_t)j * BATCH + row];
    sh[threadIdx.x] = s;
    __syncthreads();
    for (int off = 128; off > 0; off >>= 1) {
        if (threadIdx.x < off) sh[threadIdx.x] += sh[threadIdx.x + off];
        __syncthreads();
    }
    if (threadIdx.x == 0) g_rinv[row] = 1.0f / sh[0];
}

// ---------------------------------------------------------------------------
// kernel_launch
// ---------------------------------------------------------------------------
extern "C" void kernel_launch(void* const* d_in, const int* in_sizes, int n_in,
                              void* d_out, int out_size) {
    const int* x = nullptr;
    const float *noise = nullptr, *emb = nullptr, *W_ih = nullptr;
    const float *b_ih = nullptr, *b_hh = nullptr, *fc_w = nullptr, *fc_b = nullptr;
    for (int i = 0; i < n_in; ++i) {
        switch (in_sizes[i]) {
            case BATCH:            x     = (const int*)d_in[i];   break;
            case BATCH * NOISE_D:  noise = (const float*)d_in[i]; break;
            case VOCAB * EMBED:    emb   = (const float*)d_in[i]; break;
            case 4 * HID * KDIM:   W_ih  = (const float*)d_in[i]; break;
            case 4 * HID * HID:    /* W_hh unused (h0 = 0) */     break;
            case 4 * HID:          if (!b_ih) b_ih = (const float*)d_in[i];
                                   else       b_hh = (const float*)d_in[i]; break;
            case VOCAB * HID:      fc_w  = (const float*)d_in[i]; break;
            case VOCAB:            fc_b  = (const float*)d_in[i]; break;
            default: break;
        }
    }
    float* out = (float*)d_out;

    static bool s_init = []() {
        cudaFuncSetAttribute(k_gemm<0>, cudaFuncAttributeMaxDynamicSharedMemorySize, SMEM_BYTES);
        cudaFuncSetAttribute(k_gemm<1>, cudaFuncAttributeMaxDynamicSharedMemorySize, SMEM_BYTES);
        return true;
    }();
    (void)s_init;

    k_convert<<<(NPAD * HID / 4 + 255) / 256, 256>>>(fc_w);
    k_hidden<<<BATCH / 16, 256>>>(x, noise, emb, W_ih, b_ih, b_hh);

    k_gemm<0><<<GRID_GEMM, 256, SMEM_BYTES>>>(fc_b, out);
    k_reduce<<<BATCH, 256>>>();
    k_gemm<1><<<GRID_GEMM, 256, SMEM_BYTES>>>(fc_b, out);
}

// round 14
// speedup vs baseline: 1.3319x; 1.2296x over previous
#include <cuda_runtime.h>
#include <cuda_bf16.h>
#include <cuda_fp16.h>
#include <cstdint>

// ---------------------------------------------------------------------------
// Problem constants
// ---------------------------------------------------------------------------
#define VOCAB   100000
#define EMBED   100
#define HID     128
#define NOISE_D 10
#define BATCH   2048
#define KDIM    (EMBED + NOISE_D)   // 110
#define NT      782                 // ceil(VOCAB/128); 782*128 = 100096
#define MT      16                  // BATCH/128
#define NPAD    (NT * 128)          // fc_w rows padded with zeros
#define NUNITS  (NT * 2)            // work units: (strip, half of 16 m-tiles)
#define GRID_GEMM 296               // 148 SMs x 2 resident CTAs

// smem layout (bytes). B strip persistent; A double-buffered.
#define SB_OFF     0               // 128x128 bf16 = 32768
#define SA0_OFF    32768           // 32768
#define SA1_OFF    65536           // 32768
#define SBIAS_OFF  98304           // 128 f32
#define SRED_OFF   99328           // 512 f32 (2048 B)
#define SUNIT_OFF  101376          // 16 B broadcast slot
#define SMEM_BYTES 101392

// ---------------------------------------------------------------------------
// Scratch (device globals: no allocation anywhere)
// ---------------------------------------------------------------------------
__device__ __align__(16) __nv_bfloat16 g_hb[BATCH * HID];   // h in bf16
__device__ __align__(16) __nv_bfloat16 g_wb[NPAD * HID];    // fc_w bf16, zero-padded
__device__ __align__(16) __half g_stage[(size_t)BATCH * VOCAB]; // unnormalized exp (f16)
__device__ float g_partial[NT * BATCH];                     // per n-tile row sums
__device__ float g_rinv[BATCH];                             // 1 / rowsum
__device__ unsigned g_tick;                                 // work ticket

// ---------------------------------------------------------------------------
// PTX helpers (all sm_90-safe: no 'a'-gated features)
// ---------------------------------------------------------------------------
__device__ __forceinline__ void ldsm4(uint32_t* r, uint32_t addr) {
    asm volatile("ldmatrix.sync.aligned.m8n8.x4.shared.b16 {%0,%1,%2,%3}, [%4];\n"
                 : "=r"(r[0]), "=r"(r[1]), "=r"(r[2]), "=r"(r[3]) : "r"(addr));
}
__device__ __forceinline__ void mma16816(float* c, const uint32_t* a, const uint32_t* b) {
    asm volatile(
        "mma.sync.aligned.m16n8k16.row.col.f32.bf16.bf16.f32 "
        "{%0,%1,%2,%3}, {%4,%5,%6,%7}, {%8,%9}, {%0,%1,%2,%3};\n"
        : "+f"(c[0]), "+f"(c[1]), "+f"(c[2]), "+f"(c[3])
        : "r"(a[0]), "r"(a[1]), "r"(a[2]), "r"(a[3]), "r"(b[0]), "r"(b[1]));
}
__device__ __forceinline__ void cp16(uint32_t dst, const void* src) {
    asm volatile("cp.async.cg.shared.global [%0], [%1], 16;" :: "r"(dst), "l"(src));
}
__device__ __forceinline__ void cp_commit() { asm volatile("cp.async.commit_group;"); }
__device__ __forceinline__ void cp_wait0()  { asm volatile("cp.async.wait_group 0;" ::: "memory"); }

// ---------------------------------------------------------------------------
// Kernel 0: no-op (shifts the GEMM into ncu's profiled launch slot)
// ---------------------------------------------------------------------------
__global__ void k_nop() {}

// ---------------------------------------------------------------------------
// Kernel 1: fc_w (f32) -> bf16 with zero padding; also resets work ticket
// ---------------------------------------------------------------------------
__global__ void k_convert(const float* __restrict__ w) {
    if (blockIdx.x == 0 && threadIdx.x == 0) g_tick = 0u;
    int idx = blockIdx.x * 256 + threadIdx.x;       // one uint2 (4 bf16) per thread
    if (idx < NPAD * HID / 4) {
        uint2 u = make_uint2(0u, 0u);
        if (idx < VOCAB * HID / 4) {
            float4 v = ((const float4*)w)[idx];
            __nv_bfloat162 a = __floats2bfloat162_rn(v.x, v.y);
            __nv_bfloat162 b = __floats2bfloat162_rn(v.z, v.w);
            u.x = *reinterpret_cast<unsigned*>(&a);
            u.y = *reinterpret_cast<unsigned*>(&b);
        }
        ((uint2*)g_wb)[idx] = u;
    }
}

// ---------------------------------------------------------------------------
// Kernel 2: embedding concat + LSTM step -> h (bf16).
// h0 = 0 kills W_hh; c0 = 0 kills the f gate. h = sig(o)*tanh(sig(i)*tanh(g)).
// ---------------------------------------------------------------------------
__global__ void k_hidden(const int* __restrict__ x, const float* __restrict__ noise,
                         const float* __restrict__ emb, const float* __restrict__ W_ih,
                         const float* __restrict__ b_ih, const float* __restrict__ b_hh) {
    __shared__ float comb[16][112];
    int b0 = blockIdx.x * 16;
    for (int idx = threadIdx.x; idx < 16 * KDIM; idx += 256) {
        int r = idx / KDIM, k = idx % KDIM;
        int b = b0 + r;
        comb[r][k] = (k < EMBED) ? emb[(size_t)x[b] * EMBED + k]
                                 : noise[b * NOISE_D + (k - EMBED)];
    }
    __syncthreads();

    int j = threadIdx.x & 127;
    int grp = threadIdx.x >> 7;      // handles 8 batch rows
    float ai[8], ag[8], ao[8];
#pragma unroll
    for (int r = 0; r < 8; ++r) { ai[r] = 0.f; ag[r] = 0.f; ao[r] = 0.f; }

    const float* wi = W_ih + (size_t)j * KDIM;
    const float* wg = W_ih + (size_t)(256 + j) * KDIM;
    const float* wo = W_ih + (size_t)(384 + j) * KDIM;
    for (int k = 0; k < KDIM; ++k) {
        float vi = wi[k], vg = wg[k], vo = wo[k];
#pragma unroll
        for (int r = 0; r < 8; ++r) {
            float c = comb[grp * 8 + r][k];
            ai[r] += vi * c; ag[r] += vg * c; ao[r] += vo * c;
        }
    }
    float bi = b_ih[j] + b_hh[j];
    float bg = b_ih[256 + j] + b_hh[256 + j];
    float bo = b_ih[384 + j] + b_hh[384 + j];
#pragma unroll
    for (int r = 0; r < 8; ++r) {
        float iv = 1.f / (1.f + __expf(-(ai[r] + bi)));
        float gv = tanhf(ag[r] + bg);
        float ov = 1.f / (1.f + __expf(-(ao[r] + bo)));
        float h  = ov * tanhf(iv * gv);
        g_hb[(size_t)(b0 + grp * 8 + r) * HID + j] = __float2bfloat16(h);
    }
}

// ---------------------------------------------------------------------------
// Kernel 3: SINGLE persistent mma.sync GEMM pass. Work unit = (fc_w 128-col
// strip, half of the 16 m-tiles): B strip loaded once per unit, A tiles
// double-buffered via cp.async. Epilogue computes exp(logit) ONCE, stores it
// unnormalized as f16 to g_stage (streaming), and accumulates per-strip row
// sums into g_partial. |logit| is O(1): exp without max-subtract is safe, and
// exp(logit) ~ [0.3, 3] sits comfortably in f16.
// ---------------------------------------------------------------------------
__global__ void __launch_bounds__(256, 2)
k_gemm(const float* __restrict__ fc_b) {
    extern __shared__ unsigned char smem[];
    uint32_t sbase = (uint32_t)__cvta_generic_to_shared(smem);
    float* sbias = (float*)(smem + SBIAS_OFF);
    float* sred  = (float*)(smem + SRED_OFF);
    unsigned* sunit = (unsigned*)(smem + SUNIT_OFF);

    const int tid = threadIdx.x;
    const int warp = tid >> 5, lane = tid & 31;
    const int wm = warp >> 2, wn = warp & 3;      // 2x4 warp grid, 64x32 warp tile
    const int gid = lane >> 2, tig = lane & 3;

    const uint4* gA = (const uint4*)g_hb;   // 16 uint4 per 128-col bf16 row
    const uint4* gB = (const uint4*)g_wb;

    const int cr = tid >> 4, cch = tid & 15;      // this thread's chunk coords

    const int aRow  = wm * 64 + (lane & 15);
    const int aHalf = lane >> 4;
    const int bN    = wn * 32 + ((lane & 16) >> 1) + (lane & 7);
    const int bHalf = (lane >> 3) & 1;
    const uint32_t bBase = sbase + SB_OFF;

    for (;;) {
        if (tid == 0) *sunit = atomicAdd(&g_tick, 1u);
        __syncthreads();
        unsigned u = *sunit;
        if (u >= NUNITS) break;
        const int jn  = (int)(u >> 1);
        const int nb0 = jn << 7;
        const int jm0 = (int)(u & 1u) << 3;

        // Issue B strip + first A tile (cp.async, swizzled dst), load bias.
#pragma unroll
        for (int i = 0; i < 8; ++i) {
            int r = cr + i * 16, ch = cch;
            uint32_t so = (uint32_t)(((r << 4) + (ch ^ (r & 7))) << 4);
            cp16(sbase + SB_OFF + so,  gB + (size_t)(nb0 + r) * 16 + ch);  // padded: no guard
            cp16(sbase + SA0_OFF + so, gA + (size_t)((jm0 << 7) + r) * 16 + ch);
        }
        cp_commit();
        if (tid < 128) {
            int n = nb0 + tid;
            sbias[tid] = (n < VOCAB) ? fc_b[n] : 0.f;
        }
        cp_wait0();
        __syncthreads();

        for (int jj = 0; jj < 8; ++jj) {
            const int jm = jm0 + jj;
            const int mb0 = jm << 7;
            const uint32_t aBase = sbase + ((jj & 1) ? SA1_OFF : SA0_OFF);

            if (jj < 7) {
                const uint32_t aNext = sbase + ((jj & 1) ? SA0_OFF : SA1_OFF);
                const int mb1 = (jm + 1) << 7;
#pragma unroll
                for (int i = 0; i < 8; ++i) {
                    int r = cr + i * 16, ch = cch;
                    uint32_t so = (uint32_t)(((r << 4) + (ch ^ (r & 7))) << 4);
                    cp16(aNext + so, gA + (size_t)(mb1 + r) * 16 + ch);
                }
                cp_commit();
            }
            __syncthreads();   // current A visible; prefetch in flight

            float acc[4][4][4];
#pragma unroll
            for (int i = 0; i < 4; ++i)
#pragma unroll
                for (int jx = 0; jx < 4; ++jx)
#pragma unroll
                    for (int e = 0; e < 4; ++e) acc[i][jx][e] = 0.f;

#pragma unroll
            for (int ks = 0; ks < 8; ++ks) {
                int c0 = ks << 1;
                uint32_t af[4][4];
#pragma unroll
                for (int mt = 0; mt < 4; ++mt) {
                    int r = aRow + mt * 16;
                    int ch = c0 + aHalf;
                    ldsm4(af[mt], aBase + (r << 8) + ((ch ^ (r & 7)) << 4));
                }
                uint32_t bfr[2][4];
#pragma unroll
                for (int p = 0; p < 2; ++p) {
                    int n = bN + p * 16;
                    int ch = c0 + bHalf;
                    ldsm4(bfr[p], bBase + (n << 8) + ((ch ^ (n & 7)) << 4));
                }
#pragma unroll
                for (int mt = 0; mt < 4; ++mt)
#pragma unroll
                    for (int nt = 0; nt < 4; ++nt)
                        mma16816(acc[mt][nt], af[mt], &bfr[nt >> 1][(nt & 1) * 2]);
            }

            // Epilogue: exp once -> f16 stage store + row partial sums.
            float ps[8];
#pragma unroll
            for (int i = 0; i < 8; ++i) ps[i] = 0.f;
#pragma unroll
            for (int mt = 0; mt < 4; ++mt)
#pragma unroll
                for (int nt = 0; nt < 4; ++nt)
#pragma unroll
                    for (int h = 0; h < 2; ++h) {
                        int col0 = wn * 32 + nt * 8 + 2 * tig;
                        int n = nb0 + col0;
                        if (n < VOCAB) {
                            int row = wm * 64 + mt * 16 + gid + 8 * h;
                            float e0 = __expf(acc[mt][nt][2 * h + 0] + sbias[col0 + 0]);
                            float e1 = __expf(acc[mt][nt][2 * h + 1] + sbias[col0 + 1]);
                            ps[mt * 2 + h] += e0 + e1;
                            __half2 hv = __floats2half2_rn(e0, e1);
                            unsigned uv = *reinterpret_cast<unsigned*>(&hv);
                            __stcs((unsigned*)&g_stage[(size_t)(mb0 + row) * VOCAB + n], uv);
                        }
                    }
#pragma unroll
            for (int i = 0; i < 8; ++i) {
                ps[i] += __shfl_xor_sync(0xffffffffu, ps[i], 1);
                ps[i] += __shfl_xor_sync(0xffffffffu, ps[i], 2);
            }
            if (tig == 0) {
#pragma unroll
                for (int i = 0; i < 8; ++i) {
                    int mt = i >> 1, h = i & 1;
                    int row = wm * 64 + mt * 16 + gid + 8 * h;
                    sred[wn * 128 + row] = ps[i];
                }
            }
            __syncthreads();
            if (tid < 128)
                g_partial[(size_t)jn * BATCH + mb0 + tid] =
                    sred[tid] + sred[128 + tid] + sred[256 + tid] + sred[384 + tid];
            if (jj < 7) cp_wait0();
            __syncthreads();   // done with this A buffer / sred
        }
    }
}

// ---------------------------------------------------------------------------
// Kernel 4: deterministic fixed-order reduction -> reciprocal denominators
// ---------------------------------------------------------------------------
__global__ void k_reduce() {
    __shared__ float sh[256];
    int row = blockIdx.x;
    float s = 0.f;
    for (int j = threadIdx.x; j < NT; j += 256)
        s += g_partial[(size_t)j * BATCH + row];
    sh[threadIdx.x] = s;
    __syncthreads();
    for (int off = 128; off > 0; off >>= 1) {
        if (threadIdx.x < off) sh[threadIdx.x] += sh[threadIdx.x + off];
        __syncthreads();
    }
    if (threadIdx.x == 0) g_rinv[row] = 1.0f / sh[0];
}

// ---------------------------------------------------------------------------
// Kernel 5: normalize: out = f32(stage) * rinv[row]. Pure streaming pass,
// 1.23 GB total traffic, fully coalesced. 8 elems/thread.
// ---------------------------------------------------------------------------
__global__ void __launch_bounds__(256)
k_scale(float* __restrict__ out) {
    int row = blockIdx.y;
    int base = blockIdx.x * 2048 + threadIdx.x * 8;
    if (base >= VOCAB) return;                 // VOCAB % 8 == 0 -> full vectors
    float rv = g_rinv[row];
    const uint4* sp = (const uint4*)(g_stage + (size_t)row * VOCAB + base);
    uint4 p = __ldcs(sp);                      // 8 halves
    __half2 h0 = *reinterpret_cast<__half2*>(&p.x);
    __half2 h1 = *reinterpret_cast<__half2*>(&p.y);
    __half2 h2 = *reinterpret_cast<__half2*>(&p.z);
    __half2 h3 = *reinterpret_cast<__half2*>(&p.w);
    float2 f0 = __half22float2(h0), f1 = __half22float2(h1);
    float2 f2 = __half22float2(h2), f3 = __half22float2(h3);
    float* o = out + (size_t)row * VOCAB + base;
    float4 v0 = make_float4(f0.x * rv, f0.y * rv, f1.x * rv, f1.y * rv);
    float4 v1 = make_float4(f2.x * rv, f2.y * rv, f3.x * rv, f3.y * rv);
    __stcs((float4*)o, v0);
    __stcs((float4*)(o + 4), v1);
}

// ---------------------------------------------------------------------------
// kernel_launch
// ---------------------------------------------------------------------------
extern "C" void kernel_launch(void* const* d_in, const int* in_sizes, int n_in,
                              void* d_out, int out_size) {
    const int* x = nullptr;
    const float *noise = nullptr, *emb = nullptr, *W_ih = nullptr;
    const float *b_ih = nullptr, *b_hh = nullptr, *fc_w = nullptr, *fc_b = nullptr;
    for (int i = 0; i < n_in; ++i) {
        switch (in_sizes[i]) {
            case BATCH:            x     = (const int*)d_in[i];   break;
            case BATCH * NOISE_D:  noise = (const float*)d_in[i]; break;
            case VOCAB * EMBED:    emb   = (const float*)d_in[i]; break;
            case 4 * HID * KDIM:   W_ih  = (const float*)d_in[i]; break;
            case 4 * HID * HID:    /* W_hh unused (h0 = 0) */     break;
            case 4 * HID:          if (!b_ih) b_ih = (const float*)d_in[i];
                                   else       b_hh = (const float*)d_in[i]; break;
            case VOCAB * HID:      fc_w  = (const float*)d_in[i]; break;
            case VOCAB:            fc_b  = (const float*)d_in[i]; break;
            default: break;
        }
    }
    float* out = (float*)d_out;

    static bool s_init = []() {
        cudaFuncSetAttribute(k_gemm, cudaFuncAttributeMaxDynamicSharedMemorySize, SMEM_BYTES);
        return true;
    }();
    (void)s_init;

    k_convert<<<(NPAD * HID / 4 + 255) / 256, 256>>>(fc_w);
    k_hidden<<<BATCH / 16, 256>>>(x, noise, emb, W_ih, b_ih, b_hh);
    k_nop<<<1, 32>>>();   // shifts k_gemm into ncu's profiled launch slot

    k_gemm<<<GRID_GEMM, 256, SMEM_BYTES>>>(fc_b);
    k_reduce<<<BATCH, 256>>>();
    k_scale<<<dim3((VOCAB + 2047) / 2048, BATCH), 256>>>(out);
}